// round 13
// baseline (speedup 1.0000x reference)
#include <cuda_runtime.h>
#include <cuda_bf16.h>
#include <cstdint>

#define EPSV 1e-8f
#define FULLMASK 0xffffffffu

constexpr int Bb = 8;
constexpr int Ss = 2048;
constexpr int Dd = 1024;
constexpr int Hh = 1024;
constexpr int Mtot = Bb * Ss;      // 16384

// ------------------------- device scratch (no allocs) -----------------------
__device__ __nv_bfloat16 g_Xhi[(size_t)Mtot * Dd];
__device__ __nv_bfloat16 g_Xlo[(size_t)Mtot * Dd];
__device__ __nv_bfloat16 g_Whi[3][(size_t)Hh * Dd];
__device__ __nv_bfloat16 g_Wlo[3][(size_t)Hh * Dd];
__device__ float g_logret[(size_t)Bb * Hh * Ss];   // [b][h][s]
__device__ float g_ninfo[(size_t)Bb * Hh * Ss];
__device__ float g_Llast[(size_t)Bb * Hh];         // per-chain total log-retention

// ------------------------------ helpers -------------------------------------
__device__ __forceinline__ uint32_t smem_u32(const void* p) {
    uint32_t a;
    asm("{ .reg .u64 t; cvta.to.shared.u64 t, %1; cvt.u32.u64 %0, t; }"
        : "=r"(a) : "l"(p));
    return a;
}
__device__ __forceinline__ void cp16(uint32_t dst, const void* src) {
    asm volatile("cp.async.cg.shared.global [%0], [%1], 16;"
                 :: "r"(dst), "l"(src) : "memory");
}
__device__ __forceinline__ void cp_commit() {
    asm volatile("cp.async.commit_group;" ::: "memory");
}
template <int N>
__device__ __forceinline__ void cp_wait() {
    asm volatile("cp.async.wait_group %0;" :: "n"(N) : "memory");
}
__device__ __forceinline__ uint32_t swz64(uint32_t x) {   // SW64 (64B rows)
    return x ^ ((x >> 3) & 0x30);
}
__device__ __forceinline__ void ldsm4(uint32_t& r0, uint32_t& r1,
                                      uint32_t& r2, uint32_t& r3, uint32_t addr) {
    asm volatile("ldmatrix.sync.aligned.m8n8.x4.shared.b16 {%0,%1,%2,%3}, [%4];"
                 : "=r"(r0), "=r"(r1), "=r"(r2), "=r"(r3) : "r"(addr));
}
__device__ __forceinline__ void mma16816(float* c,
                                         uint32_t a0, uint32_t a1, uint32_t a2, uint32_t a3,
                                         uint32_t b0, uint32_t b1) {
    asm volatile(
        "mma.sync.aligned.m16n8k16.row.col.f32.bf16.bf16.f32 "
        "{%0,%1,%2,%3}, {%4,%5,%6,%7}, {%8,%9}, {%0,%1,%2,%3};"
        : "+f"(c[0]), "+f"(c[1]), "+f"(c[2]), "+f"(c[3])
        : "r"(a0), "r"(a1), "r"(a2), "r"(a3), "r"(b0), "r"(b1));
}

// -------------------------- fused conversion kernel --------------------------
__device__ __forceinline__ void split4(const float* __restrict__ src,
                                       __nv_bfloat16* __restrict__ dhi,
                                       __nv_bfloat16* __restrict__ dlo,
                                       size_t i) {
    float4 v = *(const float4*)(src + i);
    float f[4] = {v.x, v.y, v.z, v.w};
    __nv_bfloat16 h[4], l[4];
#pragma unroll
    for (int j = 0; j < 4; ++j) {
        h[j] = __float2bfloat16_rn(f[j]);
        l[j] = __float2bfloat16_rn(f[j] - __bfloat162float(h[j]));
    }
    *(uint2*)(dhi + i) = *(uint2*)h;
    *(uint2*)(dlo + i) = *(uint2*)l;
}

__global__ __launch_bounds__(256) void convert_all_kernel(
    const float* __restrict__ X,
    const float* __restrict__ Wf,
    const float* __restrict__ Wi,
    const float* __restrict__ Wh)
{
    const unsigned bid = blockIdx.x;
    if (bid < 8u) {
        float4 z = {0.f, 0.f, 0.f, 0.f};
        *(float4*)(g_Llast + ((size_t)bid * 256 + threadIdx.x) * 4) = z;
    }
    if (bid < 16384u) {
        size_t i = ((size_t)bid * 256 + threadIdx.x) * 4;
        split4(X, g_Xhi, g_Xlo, i);
    } else {
        const unsigned wb = bid - 16384u;
        const int gate = wb >> 10;                         // 0..2
        size_t i = ((size_t)(wb & 1023u) * 256 + threadIdx.x) * 4;
        const float* W = (gate == 0) ? Wf : (gate == 1) ? Wi : Wh;
        split4(W, g_Whi[gate], g_Wlo[gate], i);
    }
}

// ------------------------------ fused GEMM -----------------------------------
// Round-12/13: occ-2 + deep pipeline. CTA tile M=128 x N=32, 3 gates, BK=32,
// 4 stages x 28 KB = 112 KB/CTA -> 2 CTAs/SM. 256 threads, warp grid 4Mx2N.
// One __syncthreads per kt; cp_wait<2> = depth-3 prefetch; &3 slot indexing.
constexpr int BK = 32;
constexpr int NKT = Dd / BK;              // 32
constexpr int NSTAGE = 4;
constexpr uint32_t STAGE_B = 28672;       // 28 KB
constexpr uint32_t OFF_XHI = 0;           // 8 KB
constexpr uint32_t OFF_XLO = 8192;        // 8 KB
constexpr uint32_t OFF_WHI = 16384;       // + g*2048, 6 KB
constexpr uint32_t OFF_WLO = 22528;       // + g*2048, 6 KB

extern __shared__ __align__(1024) char dynsmem[];

__device__ __forceinline__ void load_stage(uint32_t sb, int tid, int kt,
                                           int row0, int col0) {
    const int kb = kt * BK;
#pragma unroll
    for (int i = 0; i < 2; ++i) {                 // X: 512 positions (hi+lo pairs)
        int c = tid + i * 256;
        int r = c >> 2, ch = c & 3;               // 128 rows x 4 chunks
        uint32_t so = swz64((uint32_t)(r * 64 + ch * 16));
        size_t ga = (size_t)(row0 + r) * Dd + kb + ch * 8;
        cp16(sb + OFF_XHI + so, g_Xhi + ga);
        cp16(sb + OFF_XLO + so, g_Xlo + ga);
    }
    {                                             // W: 384 positions
        int d = tid;
        {
            int r = d >> 2, ch = d & 3;           // r 0..63
            int g = r >> 5, n = r & 31;
            uint32_t so = (uint32_t)(g * 2048) + swz64((uint32_t)(n * 64 + ch * 16));
            size_t gb = (size_t)(col0 + n) * Dd + kb + ch * 8;
            cp16(sb + OFF_WHI + so, g_Whi[g] + gb);
            cp16(sb + OFF_WLO + so, g_Wlo[g] + gb);
        }
        d = tid + 256;
        if (d < 384) {
            int r = d >> 2, ch = d & 3;           // r 64..95
            int g = r >> 5, n = r & 31;
            uint32_t so = (uint32_t)(g * 2048) + swz64((uint32_t)(n * 64 + ch * 16));
            size_t gb = (size_t)(col0 + n) * Dd + kb + ch * 8;
            cp16(sb + OFF_WHI + so, g_Whi[g] + gb);
            cp16(sb + OFF_WLO + so, g_Wlo[g] + gb);
        }
    }
}

__global__ __launch_bounds__(256, 2) void gemm_fused_kernel(
    const float* __restrict__ bF,
    const float* __restrict__ bI,
    const float* __restrict__ bH)
{
    const int tid  = threadIdx.x;
    const int lane = tid & 31;
    const int wid  = tid >> 5;              // 0..7
    const int col0 = blockIdx.x * 32;       // h
    const int row0 = blockIdx.y * 128;      // m = b*S+s

    const int warpM = wid >> 1;             // 0..3
    const int warpN = wid & 1;              // 0..1
    const int m0w = warpM * 32;
    const int n0w = warpN * 16;

    const uint32_t sbase = smem_u32(dynsmem);

    const int rA0 = m0w + (lane & 15);
    const int rA1 = rA0 + 16;
    const uint32_t cbA = (uint32_t)(lane >> 4) * 16;
    const int rB0 = n0w + (lane >> 4) * 8 + (lane & 7);   // 16 n rows
    const uint32_t cbB = (uint32_t)((lane >> 3) & 1) * 16;

    float acc[3][2][2][4];
#pragma unroll
    for (int g = 0; g < 3; ++g)
#pragma unroll
        for (int ms = 0; ms < 2; ++ms)
#pragma unroll
            for (int ns = 0; ns < 2; ++ns)
#pragma unroll
                for (int j = 0; j < 4; ++j) acc[g][ms][ns][j] = 0.0f;

    // prologue: fill 3 stages
#pragma unroll
    for (int p = 0; p < 3; ++p) {
        load_stage(sbase + (uint32_t)p * STAGE_B, tid, p, row0, col0);
        cp_commit();
    }

    for (int kt = 0; kt < NKT; ++kt) {
        cp_wait<2>();          // stage kt resident
        __syncthreads();       // all warps done reading slot (kt+3)&3's old data

        if (kt + 3 < NKT)
            load_stage(sbase + (uint32_t)((kt + 3) & 3) * STAGE_B, tid, kt + 3, row0, col0);
        cp_commit();           // unconditional: keeps group-count invariant

        const uint32_t sb = sbase + (uint32_t)(kt & 3) * STAGE_B;
#pragma unroll
        for (int ks = 0; ks < 2; ++ks) {
            const uint32_t kofs = (uint32_t)ks * 32;
            uint32_t ah[8], al[8];
            ldsm4(ah[0], ah[1], ah[2], ah[3],
                  sb + OFF_XHI + swz64((uint32_t)rA0 * 64 + kofs + cbA));
            ldsm4(ah[4], ah[5], ah[6], ah[7],
                  sb + OFF_XHI + swz64((uint32_t)rA1 * 64 + kofs + cbA));
            ldsm4(al[0], al[1], al[2], al[3],
                  sb + OFF_XLO + swz64((uint32_t)rA0 * 64 + kofs + cbA));
            ldsm4(al[4], al[5], al[6], al[7],
                  sb + OFF_XLO + swz64((uint32_t)rA1 * 64 + kofs + cbA));
#pragma unroll
            for (int g = 0; g < 3; ++g) {
                const uint32_t whb = sb + OFF_WHI + (uint32_t)g * 2048;
                const uint32_t wlb = sb + OFF_WLO + (uint32_t)g * 2048;
                uint32_t bh[4], bl[4];
                ldsm4(bh[0], bh[1], bh[2], bh[3], whb + swz64((uint32_t)rB0 * 64 + kofs + cbB));
                ldsm4(bl[0], bl[1], bl[2], bl[3], wlb + swz64((uint32_t)rB0 * 64 + kofs + cbB));
#pragma unroll
                for (int ms = 0; ms < 2; ++ms) {
                    const uint32_t* A_hi = ah + ms * 4;
                    const uint32_t* A_lo = al + ms * 4;
#pragma unroll
                    for (int ns = 0; ns < 2; ++ns) {
                        float* c = acc[g][ms][ns];
                        mma16816(c, A_hi[0], A_hi[1], A_hi[2], A_hi[3], bh[ns * 2], bh[ns * 2 + 1]);
                        mma16816(c, A_hi[0], A_hi[1], A_hi[2], A_hi[3], bl[ns * 2], bl[ns * 2 + 1]);
                        mma16816(c, A_lo[0], A_lo[1], A_lo[2], A_lo[3], bh[ns * 2], bh[ns * 2 + 1]);
                    }
                }
            }
        }
    }
    cp_wait<0>();
    __syncthreads();

    // ---------------- epilogue: gates -> logret/ninfo ([B,H,S]) --------------
    const int bidx = row0 >> 11;
    const int s0   = row0 & (Ss - 1);
    float* tileL = (float*)dynsmem;                  // [32][129]
    float* tileN = (float*)dynsmem + 32 * 129;       // [32][129]

    float bfv[4], biv[4], bhb[4];
#pragma unroll
    for (int ns = 0; ns < 2; ++ns)
#pragma unroll
        for (int q = 0; q < 2; ++q) {
            const int nl = n0w + ns * 8 + (lane & 3) * 2 + q;
            bfv[ns * 2 + q] = __ldg(bF + col0 + nl);
            biv[ns * 2 + q] = __ldg(bI + col0 + nl);
            bhb[ns * 2 + q] = __ldg(bH + col0 + nl);
        }

#pragma unroll
    for (int ms = 0; ms < 2; ++ms)
#pragma unroll
        for (int ns = 0; ns < 2; ++ns)
#pragma unroll
            for (int j = 0; j < 4; ++j) {
                const int nl = n0w + ns * 8 + (lane & 3) * 2 + (j & 1);
                const int ml = m0w + ms * 16 + (j >> 1) * 8 + (lane >> 2);
                const int bi4 = ns * 2 + (j & 1);
                float zf = acc[0][ms][ns][j] + bfv[bi4];
                float zi = acc[1][ms][ns][j] + biv[bi4];
                float fg = 1.0f / (1.0f + expf(-zf));
                float ig = 1.0f / (1.0f + expf(-zi));
                float gs = fg + ig + EPSV;
                float zh = acc[2][ms][ns][j] + bhb[bi4];
                tileL[nl * 129 + ml] = logf(fg / gs + EPSV);
                tileN[nl * 129 + ml] = (ig / gs) * zh;
            }
    __syncthreads();

    // per-(b,h) partial Llast over this tile's 128 timesteps -> atomic accumulate
    {
        const int nl  = tid >> 3;          // 0..31
        const int seg = tid & 7;           // 8 segments of 16 timesteps
        float ps = 0.0f;
#pragma unroll
        for (int k = 0; k < 16; ++k) ps += tileL[nl * 129 + seg * 16 + k];
#pragma unroll
        for (int o = 4; o; o >>= 1) ps += __shfl_down_sync(FULLMASK, ps, o, 8);
        if (seg == 0)
            atomicAdd(&g_Llast[(size_t)bidx * Hh + col0 + nl], ps);
    }

#pragma unroll
    for (int r = 0; r < 16; ++r) {
        int idx = r * 256 + tid;
        int nl = idx >> 7;                  // 0..31
        int ml = idx & 127;
        size_t off = ((size_t)(bidx * Hh + col0 + nl)) * Ss + s0 + ml;
        g_logret[off] = tileL[nl * 129 + ml];
        g_ninfo[off]  = tileN[nl * 129 + ml];
    }
}

// ------------------------------- scan kernel ---------------------------------
// Llast precomputed by GEMM epilogue; float4 per lane.
__global__ __launch_bounds__(1024) void scan_kernel(
    const float* __restrict__ h0,
    float* __restrict__ out)
{
    __shared__ float tile[128][33];

    const int b    = blockIdx.y;
    const int hc0  = blockIdx.x * 32;
    const int w    = threadIdx.x >> 5;
    const int lane = threadIdx.x & 31;
    const int h    = hc0 + w;

    const size_t base = ((size_t)(b * Hh + h)) * Ss;
    const float* lrp = g_logret + base;
    const float* nfp = g_ninfo + base;
    const float hinit = h0[b * Hh + h];
    const float Llast = g_Llast[(size_t)b * Hh + h];

    float carryL = 0.0f;
    float carryH = 0.0f;
    for (int t0 = 0; t0 < Ss; t0 += 128) {
        float4 lr4 = *(const float4*)(lrp + t0 + lane * 4);
        float4 nf4 = *(const float4*)(nfp + t0 + lane * 4);

        float p0 = lr4.x;
        float p1 = p0 + lr4.y;
        float p2 = p1 + lr4.z;
        float p3 = p2 + lr4.w;

        float incl = p3;
#pragma unroll
        for (int o = 1; o < 32; o <<= 1) {
            float v = __shfl_up_sync(FULLMASK, incl, o);
            if (lane >= o) incl += v;
        }
        const float baseL = carryL + (incl - p3);

        float Lp[4] = {baseL, baseL + p0, baseL + p1, baseL + p2};
        float Lt[4] = {baseL + p0, baseL + p1, baseL + p2, baseL + p3};
        float nf[4] = {nf4.x, nf4.y, nf4.z, nf4.w};

        float tm[4];
#pragma unroll
        for (int j = 0; j < 4; ++j) tm[j] = expf(Llast - Lp[j]) * nf[j];

        float q0 = tm[0];
        float q1 = q0 + tm[1];
        float q2 = q1 + tm[2];
        float q3 = q2 + tm[3];

        float inclT = q3;
#pragma unroll
        for (int o = 1; o < 32; o <<= 1) {
            float v = __shfl_up_sync(FULLMASK, inclT, o);
            if (lane >= o) inclT += v;
        }
        const float baseH = carryH + (inclT - q3);

        float q[4] = {q0, q1, q2, q3};
#pragma unroll
        for (int j = 0; j < 4; ++j)
            tile[lane * 4 + j][w] = baseH + q[j] + expf(Lt[j]) * hinit;

        carryL += __shfl_sync(FULLMASK, incl, 31);
        carryH += __shfl_sync(FULLMASK, inclT, 31);

        __syncthreads();
#pragma unroll
        for (int r = 0; r < 4; ++r) {
            int tl = r * 32 + w;
            out[((size_t)b * Ss + t0 + tl) * Hh + hc0 + lane] = tile[tl][lane];
        }
        __syncthreads();
    }
}

// -----------------------------------------------------------------------------
extern "C" void kernel_launch(void* const* d_in, const int* in_sizes, int n_in,
                              void* d_out, int out_size)
{
    const float* X  = (const float*)d_in[0];
    const float* h0 = (const float*)d_in[1];
    const float* Wf = (const float*)d_in[2];
    const float* bf = (const float*)d_in[3];
    const float* Wi = (const float*)d_in[4];
    const float* bi = (const float*)d_in[5];
    const float* Wh = (const float*)d_in[6];
    const float* bh = (const float*)d_in[7];
    float* out = (float*)d_out;

    cudaFuncSetAttribute(gemm_fused_kernel,
                         cudaFuncAttributeMaxDynamicSharedMemorySize,
                         NSTAGE * STAGE_B);

    convert_all_kernel<<<19456, 256>>>(X, Wf, Wi, Wh);

    dim3 gg(Hh / 32, Mtot / 128);       // (32, 128), n-fastest for X reuse
    gemm_fused_kernel<<<gg, 256, NSTAGE * STAGE_B>>>(bf, bi, bh);

    dim3 gs(Hh / 32, Bb);               // (32, 8)
    scan_kernel<<<gs, 1024>>>(h0, out);
}

// round 14
// speedup vs baseline: 1.0969x; 1.0969x over previous
#include <cuda_runtime.h>
#include <cuda_bf16.h>
#include <cstdint>

#define EPSV 1e-8f
#define FULLMASK 0xffffffffu

constexpr int Bb = 8;
constexpr int Ss = 2048;
constexpr int Dd = 1024;
constexpr int Hh = 1024;
constexpr int Mtot = Bb * Ss;      // 16384

// ------------------------- device scratch (no allocs) -----------------------
__device__ __nv_bfloat16 g_Xhi[(size_t)Mtot * Dd];
__device__ __nv_bfloat16 g_Xlo[(size_t)Mtot * Dd];
__device__ __nv_bfloat16 g_Whi[3][(size_t)Hh * Dd];
__device__ __nv_bfloat16 g_Wlo[3][(size_t)Hh * Dd];
__device__ float g_logret[(size_t)Bb * Hh * Ss];   // [b][h][s]
__device__ float g_ninfo[(size_t)Bb * Hh * Ss];
__device__ float g_Llast[(size_t)Bb * Hh];         // per-chain total log-retention

// ------------------------------ helpers -------------------------------------
__device__ __forceinline__ uint32_t smem_u32(const void* p) {
    uint32_t a;
    asm("{ .reg .u64 t; cvta.to.shared.u64 t, %1; cvt.u32.u64 %0, t; }"
        : "=r"(a) : "l"(p));
    return a;
}
__device__ __forceinline__ void cp16(uint32_t dst, const void* src) {
    asm volatile("cp.async.cg.shared.global [%0], [%1], 16;"
                 :: "r"(dst), "l"(src) : "memory");
}
__device__ __forceinline__ void cp_commit() {
    asm volatile("cp.async.commit_group;" ::: "memory");
}
template <int N>
__device__ __forceinline__ void cp_wait() {
    asm volatile("cp.async.wait_group %0;" :: "n"(N) : "memory");
}
__device__ __forceinline__ uint32_t swz(uint32_t x) {   // SW128
    return x ^ ((x >> 3) & 0x70);
}
__device__ __forceinline__ void ldsm4(uint32_t& r0, uint32_t& r1,
                                      uint32_t& r2, uint32_t& r3, uint32_t addr) {
    asm volatile("ldmatrix.sync.aligned.m8n8.x4.shared.b16 {%0,%1,%2,%3}, [%4];"
                 : "=r"(r0), "=r"(r1), "=r"(r2), "=r"(r3) : "r"(addr));
}
__device__ __forceinline__ void mma16816(float* c,
                                         uint32_t a0, uint32_t a1, uint32_t a2, uint32_t a3,
                                         uint32_t b0, uint32_t b1) {
    asm volatile(
        "mma.sync.aligned.m16n8k16.row.col.f32.bf16.bf16.f32 "
        "{%0,%1,%2,%3}, {%4,%5,%6,%7}, {%8,%9}, {%0,%1,%2,%3};"
        : "+f"(c[0]), "+f"(c[1]), "+f"(c[2]), "+f"(c[3])
        : "r"(a0), "r"(a1), "r"(a2), "r"(a3), "r"(b0), "r"(b1));
}

// -------------------------- fused conversion kernel --------------------------
// 8 floats (2x float4) per thread for MLP=2 on the load side.
__device__ __forceinline__ void split8(const float* __restrict__ src,
                                       __nv_bfloat16* __restrict__ dhi,
                                       __nv_bfloat16* __restrict__ dlo,
                                       size_t i) {
    float4 v0 = *(const float4*)(src + i);
    float4 v1 = *(const float4*)(src + i + 4);
    float f[8] = {v0.x, v0.y, v0.z, v0.w, v1.x, v1.y, v1.z, v1.w};
    __nv_bfloat16 h[8], l[8];
#pragma unroll
    for (int j = 0; j < 8; ++j) {
        h[j] = __float2bfloat16_rn(f[j]);
        l[j] = __float2bfloat16_rn(f[j] - __bfloat162float(h[j]));
    }
    *(uint4*)(dhi + i) = *(uint4*)h;
    *(uint4*)(dlo + i) = *(uint4*)l;
}

// Blocks [0, 8192): X (8 floats/thread). Blocks [8192, 9728): W gates (512 each).
__global__ __launch_bounds__(256) void convert_all_kernel(
    const float* __restrict__ X,
    const float* __restrict__ Wf,
    const float* __restrict__ Wi,
    const float* __restrict__ Wh)
{
    const unsigned bid = blockIdx.x;
    if (bid < 8u) {
        float4 z = {0.f, 0.f, 0.f, 0.f};
        *(float4*)(g_Llast + ((size_t)bid * 256 + threadIdx.x) * 4) = z;
    }
    if (bid < 8192u) {
        size_t i = ((size_t)bid * 256 + threadIdx.x) * 8;
        split8(X, g_Xhi, g_Xlo, i);
    } else {
        const unsigned wb = bid - 8192u;
        const int gate = wb >> 9;                          // 0..2 (512 blocks each)
        size_t i = ((size_t)(wb & 511u) * 256 + threadIdx.x) * 8;
        const float* W = (gate == 0) ? Wf : (gate == 1) ? Wi : Wh;
        split8(W, g_Whi[gate], g_Wlo[gate], i);
    }
}

// ------------------------------ fused GEMM -----------------------------------
// Proven r11 optimum: CTA tile M=128 x N=32, 3 gates, BK=64,
// 2 stages of 56 KB -> 112 KB/CTA -> 2 CTAs/SM. 256 threads, warp grid 4Mx2N.
// Epilogue reduces per-(b,h) logret partials -> atomicAdd g_Llast.
constexpr int BK = 64;
constexpr int NK = Dd / BK;               // 16
constexpr uint32_t STAGE_B = 57344;       // 56 KB
constexpr uint32_t OFF_XHI = 0;           // 16 KB
constexpr uint32_t OFF_XLO = 16384;       // 16 KB
constexpr uint32_t OFF_WHI = 32768;       // + g*4096, 12 KB
constexpr uint32_t OFF_WLO = 45056;       // + g*4096, 12 KB

extern __shared__ __align__(1024) char dynsmem[];

__device__ __forceinline__ void load_stage(uint32_t sb, int tid, int kt,
                                           int row0, int col0) {
    const int kb = kt * BK;
#pragma unroll
    for (int i = 0; i < 4; ++i) {                 // X: 1024 positions
        int c = tid + i * 256;
        int r = c >> 3, ch = c & 7;
        uint32_t so = swz((uint32_t)(r * 128 + ch * 16));
        size_t ga = (size_t)(row0 + r) * Dd + kb + ch * 8;
        cp16(sb + OFF_XHI + so, g_Xhi + ga);
        cp16(sb + OFF_XLO + so, g_Xlo + ga);
    }
#pragma unroll
    for (int i = 0; i < 3; ++i) {                 // W: 768 positions (3 gates x 32 n)
        int d = tid + i * 256;
        int r = d >> 3, ch = d & 7;               // r 0..95
        int g = r >> 5, n = r & 31;
        uint32_t so = (uint32_t)(g * 4096) + swz((uint32_t)(n * 128 + ch * 16));
        size_t gb = (size_t)(col0 + n) * Dd + kb + ch * 8;
        cp16(sb + OFF_WHI + so, g_Whi[g] + gb);
        cp16(sb + OFF_WLO + so, g_Wlo[g] + gb);
    }
}

__global__ __launch_bounds__(256, 2) void gemm_fused_kernel(
    const float* __restrict__ bF,
    const float* __restrict__ bI,
    const float* __restrict__ bH)
{
    const int tid  = threadIdx.x;
    const int lane = tid & 31;
    const int wid  = tid >> 5;              // 0..7
    const int col0 = blockIdx.x * 32;       // h
    const int row0 = blockIdx.y * 128;      // m = b*S+s

    const int warpM = wid >> 1;             // 0..3
    const int warpN = wid & 1;              // 0..1
    const int m0w = warpM * 32;
    const int n0w = warpN * 16;

    const uint32_t sbase = smem_u32(dynsmem);

    const int rA0 = m0w + (lane & 15);
    const int rA1 = rA0 + 16;
    const uint32_t cbA = (uint32_t)(lane >> 4) * 16;
    const int rB0 = n0w + (lane >> 4) * 8 + (lane & 7);   // 16 n rows
    const uint32_t cbB = (uint32_t)((lane >> 3) & 1) * 16;

    float acc[3][2][2][4];
#pragma unroll
    for (int g = 0; g < 3; ++g)
#pragma unroll
        for (int ms = 0; ms < 2; ++ms)
#pragma unroll
            for (int ns = 0; ns < 2; ++ns)
#pragma unroll
                for (int j = 0; j < 4; ++j) acc[g][ms][ns][j] = 0.0f;

    load_stage(sbase, tid, 0, row0, col0);
    cp_commit();

    for (int kt = 0; kt < NK; ++kt) {
        const uint32_t sb = sbase + (uint32_t)(kt & 1) * STAGE_B;
        if (kt + 1 < NK) {
            load_stage(sbase + (uint32_t)((kt + 1) & 1) * STAGE_B, tid, kt + 1, row0, col0);
            cp_commit();
            cp_wait<1>();
        } else {
            cp_wait<0>();
        }
        __syncthreads();

#pragma unroll
        for (int ks = 0; ks < 4; ++ks) {
            const uint32_t kofs = (uint32_t)ks * 32;
            uint32_t ah[8], al[8];
            ldsm4(ah[0], ah[1], ah[2], ah[3],
                  sb + OFF_XHI + swz((uint32_t)rA0 * 128 + kofs + cbA));
            ldsm4(ah[4], ah[5], ah[6], ah[7],
                  sb + OFF_XHI + swz((uint32_t)rA1 * 128 + kofs + cbA));
            ldsm4(al[0], al[1], al[2], al[3],
                  sb + OFF_XLO + swz((uint32_t)rA0 * 128 + kofs + cbA));
            ldsm4(al[4], al[5], al[6], al[7],
                  sb + OFF_XLO + swz((uint32_t)rA1 * 128 + kofs + cbA));
#pragma unroll
            for (int g = 0; g < 3; ++g) {
                const uint32_t whb = sb + OFF_WHI + (uint32_t)g * 4096;
                const uint32_t wlb = sb + OFF_WLO + (uint32_t)g * 4096;
                uint32_t bh[4], bl[4];
                ldsm4(bh[0], bh[1], bh[2], bh[3], whb + swz((uint32_t)rB0 * 128 + kofs + cbB));
                ldsm4(bl[0], bl[1], bl[2], bl[3], wlb + swz((uint32_t)rB0 * 128 + kofs + cbB));
#pragma unroll
                for (int ms = 0; ms < 2; ++ms) {
                    const uint32_t* A_hi = ah + ms * 4;
                    const uint32_t* A_lo = al + ms * 4;
#pragma unroll
                    for (int ns = 0; ns < 2; ++ns) {
                        float* c = acc[g][ms][ns];
                        mma16816(c, A_hi[0], A_hi[1], A_hi[2], A_hi[3], bh[ns * 2], bh[ns * 2 + 1]);
                        mma16816(c, A_hi[0], A_hi[1], A_hi[2], A_hi[3], bl[ns * 2], bl[ns * 2 + 1]);
                        mma16816(c, A_lo[0], A_lo[1], A_lo[2], A_lo[3], bh[ns * 2], bh[ns * 2 + 1]);
                    }
                }
            }
        }
        __syncthreads();
    }

    // ---------------- epilogue: gates -> logret/ninfo ([B,H,S]) --------------
    const int bidx = row0 >> 11;
    const int s0   = row0 & (Ss - 1);
    float* tileL = (float*)dynsmem;                  // [32][129]
    float* tileN = (float*)dynsmem + 32 * 129;       // [32][129]

    float bfv[4], biv[4], bhb[4];
#pragma unroll
    for (int ns = 0; ns < 2; ++ns)
#pragma unroll
        for (int q = 0; q < 2; ++q) {
            const int nl = n0w + ns * 8 + (lane & 3) * 2 + q;
            bfv[ns * 2 + q] = __ldg(bF + col0 + nl);
            biv[ns * 2 + q] = __ldg(bI + col0 + nl);
            bhb[ns * 2 + q] = __ldg(bH + col0 + nl);
        }

#pragma unroll
    for (int ms = 0; ms < 2; ++ms)
#pragma unroll
        for (int ns = 0; ns < 2; ++ns)
#pragma unroll
            for (int j = 0; j < 4; ++j) {
                const int nl = n0w + ns * 8 + (lane & 3) * 2 + (j & 1);
                const int ml = m0w + ms * 16 + (j >> 1) * 8 + (lane >> 2);
                const int bi4 = ns * 2 + (j & 1);
                float zf = acc[0][ms][ns][j] + bfv[bi4];
                float zi = acc[1][ms][ns][j] + biv[bi4];
                float fg = 1.0f / (1.0f + expf(-zf));
                float ig = 1.0f / (1.0f + expf(-zi));
                float gs = fg + ig + EPSV;
                float zh = acc[2][ms][ns][j] + bhb[bi4];
                tileL[nl * 129 + ml] = logf(fg / gs + EPSV);
                tileN[nl * 129 + ml] = (ig / gs) * zh;
            }
    __syncthreads();

    // per-(b,h) partial Llast over this tile's 128 timesteps -> atomic accumulate
    {
        const int nl  = tid >> 3;          // 0..31
        const int seg = tid & 7;           // 8 segments of 16 timesteps
        float ps = 0.0f;
#pragma unroll
        for (int k = 0; k < 16; ++k) ps += tileL[nl * 129 + seg * 16 + k];
#pragma unroll
        for (int o = 4; o; o >>= 1) ps += __shfl_down_sync(FULLMASK, ps, o, 8);
        if (seg == 0)
            atomicAdd(&g_Llast[(size_t)bidx * Hh + col0 + nl], ps);
    }

#pragma unroll
    for (int r = 0; r < 16; ++r) {
        int idx = r * 256 + tid;
        int nl = idx >> 7;                  // 0..31
        int ml = idx & 127;
        size_t off = ((size_t)(bidx * Hh + col0 + nl)) * Ss + s0 + ml;
        g_logret[off] = tileL[nl * 129 + ml];
        g_ninfo[off]  = tileN[nl * 129 + ml];
    }
}

// ------------------------------- scan kernel ---------------------------------
// Llast precomputed by GEMM epilogue; float4 per lane.
__global__ __launch_bounds__(1024) void scan_kernel(
    const float* __restrict__ h0,
    float* __restrict__ out)
{
    __shared__ float tile[128][33];

    const int b    = blockIdx.y;
    const int hc0  = blockIdx.x * 32;
    const int w    = threadIdx.x >> 5;
    const int lane = threadIdx.x & 31;
    const int h    = hc0 + w;

    const size_t base = ((size_t)(b * Hh + h)) * Ss;
    const float* lrp = g_logret + base;
    const float* nfp = g_ninfo + base;
    const float hinit = h0[b * Hh + h];
    const float Llast = g_Llast[(size_t)b * Hh + h];

    float carryL = 0.0f;
    float carryH = 0.0f;
    for (int t0 = 0; t0 < Ss; t0 += 128) {
        float4 lr4 = *(const float4*)(lrp + t0 + lane * 4);
        float4 nf4 = *(const float4*)(nfp + t0 + lane * 4);

        float p0 = lr4.x;
        float p1 = p0 + lr4.y;
        float p2 = p1 + lr4.z;
        float p3 = p2 + lr4.w;

        float incl = p3;
#pragma unroll
        for (int o = 1; o < 32; o <<= 1) {
            float v = __shfl_up_sync(FULLMASK, incl, o);
            if (lane >= o) incl += v;
        }
        const float baseL = carryL + (incl - p3);

        float Lp[4] = {baseL, baseL + p0, baseL + p1, baseL + p2};
        float Lt[4] = {baseL + p0, baseL + p1, baseL + p2, baseL + p3};
        float nf[4] = {nf4.x, nf4.y, nf4.z, nf4.w};

        float tm[4];
#pragma unroll
        for (int j = 0; j < 4; ++j) tm[j] = expf(Llast - Lp[j]) * nf[j];

        float q0 = tm[0];
        float q1 = q0 + tm[1];
        float q2 = q1 + tm[2];
        float q3 = q2 + tm[3];

        float inclT = q3;
#pragma unroll
        for (int o = 1; o < 32; o <<= 1) {
            float v = __shfl_up_sync(FULLMASK, inclT, o);
            if (lane >= o) inclT += v;
        }
        const float baseH = carryH + (inclT - q3);

        float q[4] = {q0, q1, q2, q3};
#pragma unroll
        for (int j = 0; j < 4; ++j)
            tile[lane * 4 + j][w] = baseH + q[j] + expf(Lt[j]) * hinit;

        carryL += __shfl_sync(FULLMASK, incl, 31);
        carryH += __shfl_sync(FULLMASK, inclT, 31);

        __syncthreads();
#pragma unroll
        for (int r = 0; r < 4; ++r) {
            int tl = r * 32 + w;
            out[((size_t)b * Ss + t0 + tl) * Hh + hc0 + lane] = tile[tl][lane];
        }
        __syncthreads();
    }
}

// -----------------------------------------------------------------------------
extern "C" void kernel_launch(void* const* d_in, const int* in_sizes, int n_in,
                              void* d_out, int out_size)
{
    const float* X  = (const float*)d_in[0];
    const float* h0 = (const float*)d_in[1];
    const float* Wf = (const float*)d_in[2];
    const float* bf = (const float*)d_in[3];
    const float* Wi = (const float*)d_in[4];
    const float* bi = (const float*)d_in[5];
    const float* Wh = (const float*)d_in[6];
    const float* bh = (const float*)d_in[7];
    float* out = (float*)d_out;

    cudaFuncSetAttribute(gemm_fused_kernel,
                         cudaFuncAttributeMaxDynamicSharedMemorySize,
                         2 * STAGE_B);

    convert_all_kernel<<<9728, 256>>>(X, Wf, Wi, Wh);

    dim3 gg(Hh / 32, Mtot / 128);       // (32, 128), n-fastest for X reuse
    gemm_fused_kernel<<<gg, 256, 2 * STAGE_B>>>(bf, bi, bh);

    dim3 gs(Hh / 32, Bb);               // (32, 8)
    scan_kernel<<<gs, 1024>>>(h0, out);
}

// round 15
// speedup vs baseline: 1.1428x; 1.0419x over previous
#include <cuda_runtime.h>
#include <cuda_bf16.h>
#include <cstdint>

#define EPSV 1e-8f
#define FULLMASK 0xffffffffu

constexpr int Bb = 8;
constexpr int Ss = 2048;
constexpr int Dd = 1024;
constexpr int Hh = 1024;
constexpr int Mtot = Bb * Ss;      // 16384

// ------------------------- device scratch (no allocs) -----------------------
__device__ __nv_bfloat16 g_Xhi[(size_t)Mtot * Dd];
__device__ __nv_bfloat16 g_Xlo[(size_t)Mtot * Dd];
__device__ __nv_bfloat16 g_Whi[3][(size_t)Hh * Dd];
__device__ __nv_bfloat16 g_Wlo[3][(size_t)Hh * Dd];
__device__ float g_logret[(size_t)Bb * Hh * Ss];   // [b][h][s]
__device__ float g_ninfo[(size_t)Bb * Hh * Ss];
__device__ float g_Llast[(size_t)Bb * Hh];         // per-chain total log-retention

// ------------------------------ helpers -------------------------------------
__device__ __forceinline__ uint32_t smem_u32(const void* p) {
    uint32_t a;
    asm("{ .reg .u64 t; cvta.to.shared.u64 t, %1; cvt.u32.u64 %0, t; }"
        : "=r"(a) : "l"(p));
    return a;
}
__device__ __forceinline__ void cp16(uint32_t dst, const void* src) {
    asm volatile("cp.async.cg.shared.global [%0], [%1], 16;"
                 :: "r"(dst), "l"(src) : "memory");
}
__device__ __forceinline__ void cp_commit() {
    asm volatile("cp.async.commit_group;" ::: "memory");
}
template <int N>
__device__ __forceinline__ void cp_wait() {
    asm volatile("cp.async.wait_group %0;" :: "n"(N) : "memory");
}
__device__ __forceinline__ uint32_t swz(uint32_t x) {   // SW128
    return x ^ ((x >> 3) & 0x70);
}
__device__ __forceinline__ void ldsm4(uint32_t& r0, uint32_t& r1,
                                      uint32_t& r2, uint32_t& r3, uint32_t addr) {
    asm volatile("ldmatrix.sync.aligned.m8n8.x4.shared.b16 {%0,%1,%2,%3}, [%4];"
                 : "=r"(r0), "=r"(r1), "=r"(r2), "=r"(r3) : "r"(addr));
}
__device__ __forceinline__ void mma16816(float* c,
                                         uint32_t a0, uint32_t a1, uint32_t a2, uint32_t a3,
                                         uint32_t b0, uint32_t b1) {
    asm volatile(
        "mma.sync.aligned.m16n8k16.row.col.f32.bf16.bf16.f32 "
        "{%0,%1,%2,%3}, {%4,%5,%6,%7}, {%8,%9}, {%0,%1,%2,%3};"
        : "+f"(c[0]), "+f"(c[1]), "+f"(c[2]), "+f"(c[3])
        : "r"(a0), "r"(a1), "r"(a2), "r"(a3), "r"(b0), "r"(b1));
}

// -------------------------- fused conversion kernel --------------------------
__device__ __forceinline__ void split8(const float* __restrict__ src,
                                       __nv_bfloat16* __restrict__ dhi,
                                       __nv_bfloat16* __restrict__ dlo,
                                       size_t i) {
    float4 v0 = *(const float4*)(src + i);
    float4 v1 = *(const float4*)(src + i + 4);
    float f[8] = {v0.x, v0.y, v0.z, v0.w, v1.x, v1.y, v1.z, v1.w};
    __nv_bfloat16 h[8], l[8];
#pragma unroll
    for (int j = 0; j < 8; ++j) {
        h[j] = __float2bfloat16_rn(f[j]);
        l[j] = __float2bfloat16_rn(f[j] - __bfloat162float(h[j]));
    }
    *(uint4*)(dhi + i) = *(uint4*)h;
    *(uint4*)(dlo + i) = *(uint4*)l;
}

// Blocks [0, 8192): X (8 floats/thread). Blocks [8192, 9728): W gates (512 each).
__global__ __launch_bounds__(256) void convert_all_kernel(
    const float* __restrict__ X,
    const float* __restrict__ Wf,
    const float* __restrict__ Wi,
    const float* __restrict__ Wh)
{
    const unsigned bid = blockIdx.x;
    if (bid < 8u) {
        float4 z = {0.f, 0.f, 0.f, 0.f};
        *(float4*)(g_Llast + ((size_t)bid * 256 + threadIdx.x) * 4) = z;
    }
    if (bid < 8192u) {
        size_t i = ((size_t)bid * 256 + threadIdx.x) * 8;
        split8(X, g_Xhi, g_Xlo, i);
    } else {
        const unsigned wb = bid - 8192u;
        const int gate = wb >> 9;                          // 0..2 (512 blocks each)
        size_t i = ((size_t)(wb & 511u) * 256 + threadIdx.x) * 8;
        const float* W = (gate == 0) ? Wf : (gate == 1) ? Wi : Wh;
        split8(W, g_Whi[gate], g_Wlo[gate], i);
    }
}

// ------------------------------ fused GEMM -----------------------------------
// Proven optimum (r11/r14): CTA tile M=128 x N=32, 3 gates, BK=64,
// 2 stages of 56 KB -> 112 KB/CTA -> 2 CTAs/SM. 256 threads, warp grid 4Mx2N.
constexpr int BK = 64;
constexpr int NK = Dd / BK;               // 16
constexpr uint32_t STAGE_B = 57344;       // 56 KB
constexpr uint32_t OFF_XHI = 0;           // 16 KB
constexpr uint32_t OFF_XLO = 16384;       // 16 KB
constexpr uint32_t OFF_WHI = 32768;       // + g*4096, 12 KB
constexpr uint32_t OFF_WLO = 45056;       // + g*4096, 12 KB

extern __shared__ __align__(1024) char dynsmem[];

__device__ __forceinline__ void load_stage(uint32_t sb, int tid, int kt,
                                           int row0, int col0) {
    const int kb = kt * BK;
#pragma unroll
    for (int i = 0; i < 4; ++i) {                 // X: 1024 positions
        int c = tid + i * 256;
        int r = c >> 3, ch = c & 7;
        uint32_t so = swz((uint32_t)(r * 128 + ch * 16));
        size_t ga = (size_t)(row0 + r) * Dd + kb + ch * 8;
        cp16(sb + OFF_XHI + so, g_Xhi + ga);
        cp16(sb + OFF_XLO + so, g_Xlo + ga);
    }
#pragma unroll
    for (int i = 0; i < 3; ++i) {                 // W: 768 positions (3 gates x 32 n)
        int d = tid + i * 256;
        int r = d >> 3, ch = d & 7;               // r 0..95
        int g = r >> 5, n = r & 31;
        uint32_t so = (uint32_t)(g * 4096) + swz((uint32_t)(n * 128 + ch * 16));
        size_t gb = (size_t)(col0 + n) * Dd + kb + ch * 8;
        cp16(sb + OFF_WHI + so, g_Whi[g] + gb);
        cp16(sb + OFF_WLO + so, g_Wlo[g] + gb);
    }
}

__global__ __launch_bounds__(256, 2) void gemm_fused_kernel(
    const float* __restrict__ bF,
    const float* __restrict__ bI,
    const float* __restrict__ bH)
{
    const int tid  = threadIdx.x;
    const int lane = tid & 31;
    const int wid  = tid >> 5;              // 0..7
    const int col0 = blockIdx.x * 32;       // h
    const int row0 = blockIdx.y * 128;      // m = b*S+s

    const int warpM = wid >> 1;             // 0..3
    const int warpN = wid & 1;              // 0..1
    const int m0w = warpM * 32;
    const int n0w = warpN * 16;

    const uint32_t sbase = smem_u32(dynsmem);

    const int rA0 = m0w + (lane & 15);
    const int rA1 = rA0 + 16;
    const uint32_t cbA = (uint32_t)(lane >> 4) * 16;
    const int rB0 = n0w + (lane >> 4) * 8 + (lane & 7);   // 16 n rows
    const uint32_t cbB = (uint32_t)((lane >> 3) & 1) * 16;

    float acc[3][2][2][4];
#pragma unroll
    for (int g = 0; g < 3; ++g)
#pragma unroll
        for (int ms = 0; ms < 2; ++ms)
#pragma unroll
            for (int ns = 0; ns < 2; ++ns)
#pragma unroll
                for (int j = 0; j < 4; ++j) acc[g][ms][ns][j] = 0.0f;

    load_stage(sbase, tid, 0, row0, col0);
    cp_commit();

    for (int kt = 0; kt < NK; ++kt) {
        const uint32_t sb = sbase + (uint32_t)(kt & 1) * STAGE_B;
        if (kt + 1 < NK) {
            load_stage(sbase + (uint32_t)((kt + 1) & 1) * STAGE_B, tid, kt + 1, row0, col0);
            cp_commit();
            cp_wait<1>();
        } else {
            cp_wait<0>();
        }
        __syncthreads();

#pragma unroll
        for (int ks = 0; ks < 4; ++ks) {
            const uint32_t kofs = (uint32_t)ks * 32;
            uint32_t ah[8], al[8];
            ldsm4(ah[0], ah[1], ah[2], ah[3],
                  sb + OFF_XHI + swz((uint32_t)rA0 * 128 + kofs + cbA));
            ldsm4(ah[4], ah[5], ah[6], ah[7],
                  sb + OFF_XHI + swz((uint32_t)rA1 * 128 + kofs + cbA));
            ldsm4(al[0], al[1], al[2], al[3],
                  sb + OFF_XLO + swz((uint32_t)rA0 * 128 + kofs + cbA));
            ldsm4(al[4], al[5], al[6], al[7],
                  sb + OFF_XLO + swz((uint32_t)rA1 * 128 + kofs + cbA));
#pragma unroll
            for (int g = 0; g < 3; ++g) {
                const uint32_t whb = sb + OFF_WHI + (uint32_t)g * 4096;
                const uint32_t wlb = sb + OFF_WLO + (uint32_t)g * 4096;
                uint32_t bh[4], bl[4];
                ldsm4(bh[0], bh[1], bh[2], bh[3], whb + swz((uint32_t)rB0 * 128 + kofs + cbB));
                ldsm4(bl[0], bl[1], bl[2], bl[3], wlb + swz((uint32_t)rB0 * 128 + kofs + cbB));
#pragma unroll
                for (int ms = 0; ms < 2; ++ms) {
                    const uint32_t* A_hi = ah + ms * 4;
                    const uint32_t* A_lo = al + ms * 4;
#pragma unroll
                    for (int ns = 0; ns < 2; ++ns) {
                        float* c = acc[g][ms][ns];
                        mma16816(c, A_hi[0], A_hi[1], A_hi[2], A_hi[3], bh[ns * 2], bh[ns * 2 + 1]);
                        mma16816(c, A_hi[0], A_hi[1], A_hi[2], A_hi[3], bl[ns * 2], bl[ns * 2 + 1]);
                        mma16816(c, A_lo[0], A_lo[1], A_lo[2], A_lo[3], bh[ns * 2], bh[ns * 2 + 1]);
                    }
                }
            }
        }
        __syncthreads();
    }

    // ---------------- epilogue: gates -> logret/ninfo ([B,H,S]) --------------
    const int bidx = row0 >> 11;
    const int s0   = row0 & (Ss - 1);
    float* tileL = (float*)dynsmem;                  // [32][129]
    float* tileN = (float*)dynsmem + 32 * 129;       // [32][129]

    float bfv[4], biv[4], bhb[4];
#pragma unroll
    for (int ns = 0; ns < 2; ++ns)
#pragma unroll
        for (int q = 0; q < 2; ++q) {
            const int nl = n0w + ns * 8 + (lane & 3) * 2 + q;
            bfv[ns * 2 + q] = __ldg(bF + col0 + nl);
            biv[ns * 2 + q] = __ldg(bI + col0 + nl);
            bhb[ns * 2 + q] = __ldg(bH + col0 + nl);
        }

#pragma unroll
    for (int ms = 0; ms < 2; ++ms)
#pragma unroll
        for (int ns = 0; ns < 2; ++ns)
#pragma unroll
            for (int j = 0; j < 4; ++j) {
                const int nl = n0w + ns * 8 + (lane & 3) * 2 + (j & 1);
                const int ml = m0w + ms * 16 + (j >> 1) * 8 + (lane >> 2);
                const int bi4 = ns * 2 + (j & 1);
                float zf = acc[0][ms][ns][j] + bfv[bi4];
                float zi = acc[1][ms][ns][j] + biv[bi4];
                float fg = 1.0f / (1.0f + expf(-zf));
                float ig = 1.0f / (1.0f + expf(-zi));
                float gs = fg + ig + EPSV;
                float zh = acc[2][ms][ns][j] + bhb[bi4];
                tileL[nl * 129 + ml] = logf(fg / gs + EPSV);
                tileN[nl * 129 + ml] = (ig / gs) * zh;
            }
    __syncthreads();

    // per-(b,h) partial Llast over this tile's 128 timesteps -> atomic accumulate
    {
        const int nl  = tid >> 3;          // 0..31
        const int seg = tid & 7;           // 8 segments of 16 timesteps
        float ps = 0.0f;
#pragma unroll
        for (int k = 0; k < 16; ++k) ps += tileL[nl * 129 + seg * 16 + k];
#pragma unroll
        for (int o = 4; o; o >>= 1) ps += __shfl_down_sync(FULLMASK, ps, o, 8);
        if (seg == 0)
            atomicAdd(&g_Llast[(size_t)bidx * Hh + col0 + nl], ps);
    }

#pragma unroll
    for (int r = 0; r < 16; ++r) {
        int idx = r * 256 + tid;
        int nl = idx >> 7;                  // 0..31
        int ml = idx & 127;
        size_t off = ((size_t)(bidx * Hh + col0 + nl)) * Ss + s0 + ml;
        g_logret[off] = tileL[nl * 129 + ml];
        g_ninfo[off]  = tileN[nl * 129 + ml];
    }
}

// ------------------------------- scan kernel ---------------------------------
// r15: 256 threads (8 chains of one b), 1024 blocks for wave balance;
// software-pipelined chunk loads; tile[8][132] with float4 stores.
__global__ __launch_bounds__(256) void scan_kernel(
    const float* __restrict__ h0,
    float* __restrict__ out)
{
    __shared__ float tile[8][132];

    const int b    = blockIdx.y;
    const int hc0  = blockIdx.x * 8;
    const int w    = threadIdx.x >> 5;      // 0..7 chain within block
    const int lane = threadIdx.x & 31;
    const int h    = hc0 + w;

    const size_t base = ((size_t)(b * Hh + h)) * Ss;
    const float* lrp = g_logret + base;
    const float* nfp = g_ninfo + base;
    const float hinit = h0[b * Hh + h];
    const float Llast = g_Llast[(size_t)b * Hh + h];

    float carryL = 0.0f;
    float carryH = 0.0f;

    float4 lr4 = *(const float4*)(lrp + lane * 4);
    float4 nf4 = *(const float4*)(nfp + lane * 4);

    for (int t0 = 0; t0 < Ss; t0 += 128) {
        // prefetch next chunk (clamped at tail; result unused on last iter)
        const int tn = (t0 + 128 < Ss) ? (t0 + 128) : t0;
        float4 lr4n = *(const float4*)(lrp + tn + lane * 4);
        float4 nf4n = *(const float4*)(nfp + tn + lane * 4);

        float p0 = lr4.x;
        float p1 = p0 + lr4.y;
        float p2 = p1 + lr4.z;
        float p3 = p2 + lr4.w;

        float incl = p3;
#pragma unroll
        for (int o = 1; o < 32; o <<= 1) {
            float v = __shfl_up_sync(FULLMASK, incl, o);
            if (lane >= o) incl += v;
        }
        const float baseL = carryL + (incl - p3);

        float Lp[4] = {baseL, baseL + p0, baseL + p1, baseL + p2};
        float Lt[4] = {baseL + p0, baseL + p1, baseL + p2, baseL + p3};
        float nf[4] = {nf4.x, nf4.y, nf4.z, nf4.w};

        float tm[4];
#pragma unroll
        for (int j = 0; j < 4; ++j) tm[j] = expf(Llast - Lp[j]) * nf[j];

        float q0 = tm[0];
        float q1 = q0 + tm[1];
        float q2 = q1 + tm[2];
        float q3 = q2 + tm[3];

        float inclT = q3;
#pragma unroll
        for (int o = 1; o < 32; o <<= 1) {
            float v = __shfl_up_sync(FULLMASK, inclT, o);
            if (lane >= o) inclT += v;
        }
        const float baseH = carryH + (inclT - q3);

        float4 hid;
        hid.x = baseH + q0 + expf(Lt[0]) * hinit;
        hid.y = baseH + q1 + expf(Lt[1]) * hinit;
        hid.z = baseH + q2 + expf(Lt[2]) * hinit;
        hid.w = baseH + q3 + expf(Lt[3]) * hinit;

        carryL += __shfl_sync(FULLMASK, incl, 31);
        carryH += __shfl_sync(FULLMASK, inclT, 31);

        // conflict-free float4 store: tile[w][lane*4 .. lane*4+3]
        *(float4*)&tile[w][lane * 4] = hid;
        __syncthreads();
        // 1024 elems = 128 t x 8 h; thread writes (t, hh): 32B-sector aligned
#pragma unroll
        for (int r = 0; r < 4; ++r) {
            int idx = r * 256 + threadIdx.x;
            int t  = idx >> 3;
            int hh = idx & 7;
            out[((size_t)b * Ss + t0 + t) * Hh + hc0 + hh] = tile[hh][t];
        }
        __syncthreads();

        lr4 = lr4n;
        nf4 = nf4n;
    }
}

// -----------------------------------------------------------------------------
extern "C" void kernel_launch(void* const* d_in, const int* in_sizes, int n_in,
                              void* d_out, int out_size)
{
    const float* X  = (const float*)d_in[0];
    const float* h0 = (const float*)d_in[1];
    const float* Wf = (const float*)d_in[2];
    const float* bf = (const float*)d_in[3];
    const float* Wi = (const float*)d_in[4];
    const float* bi = (const float*)d_in[5];
    const float* Wh = (const float*)d_in[6];
    const float* bh = (const float*)d_in[7];
    float* out = (float*)d_out;

    cudaFuncSetAttribute(gemm_fused_kernel,
                         cudaFuncAttributeMaxDynamicSharedMemorySize,
                         2 * STAGE_B);

    convert_all_kernel<<<9728, 256>>>(X, Wf, Wi, Wh);

    dim3 gg(Hh / 32, Mtot / 128);       // (32, 128), n-fastest for X reuse
    gemm_fused_kernel<<<gg, 256, 2 * STAGE_B>>>(bf, bi, bh);

    dim3 gs(Hh / 8, Bb);                // (128, 8) = 1024 blocks
    scan_kernel<<<gs, 256>>>(h0, out);
}